// round 1
// baseline (speedup 1.0000x reference)
#include <cuda_runtime.h>
#include <math.h>

#define N_OBJ   2048
#define N_REL   32768
#define FEAT    2048
#define DIM     512
#define NC_OBJ  151
#define NC_PRED 51

// ---------------- scratch (static device globals; no allocation) -------------
__device__ __align__(128) float g_hpred [N_REL*DIM];   // pred MLP hidden
__device__ __align__(128) float g_pfeatA[N_REL*DIM];
__device__ __align__(128) float g_pfeatB[N_REL*DIM];
__device__ __align__(128) float g_hobj  [N_OBJ*DIM];
__device__ __align__(128) float g_ofeatA[N_OBJ*DIM];
__device__ __align__(128) float g_ofeatB[N_OBJ*DIM];
__device__ __align__(128) float g_fco0  [N_OBJ*DIM];
__device__ __align__(128) float g_fco1  [N_OBJ*DIM];
__device__ __align__(128) float g_acc0  [N_OBJ*DIM];
__device__ __align__(128) float g_acc1  [N_OBJ*DIM];
__device__ __align__(128) float g_osA   [N_OBJ*NC_OBJ];
__device__ __align__(128) float g_osB   [N_OBJ*NC_OBJ];
__device__ __align__(128) float g_psA   [N_REL*NC_PRED];
__device__ __align__(128) float g_psB   [N_REL*NC_PRED];
__device__ __align__(128) float g_sacc0 [N_OBJ*NC_OBJ];
__device__ __align__(128) float g_sacc1 [N_OBJ*NC_OBJ];
__device__ __align__(128) float g_fcs0  [N_OBJ*NC_PRED];
__device__ __align__(128) float g_fcs1  [N_OBJ*NC_PRED];
__device__ __align__(128) float g_deg   [2*N_OBJ];      // [0:2048)=subj deg, [2048:4096)=obj deg

// ---------------- small utility kernels --------------------------------------
__global__ void zero_kernel(float* p, int n) {
    int i = blockIdx.x * blockDim.x + threadIdx.x;
    if (i < n) p[i] = 0.0f;
}

__global__ void copy_kernel(float* __restrict__ dst, const float* __restrict__ src, int n) {
    int i = blockIdx.x * blockDim.x + threadIdx.x;
    if (i < n) dst[i] = src[i];
}

__global__ void deg_kernel(const int* __restrict__ rel, float* __restrict__ deg) {
    int r = blockIdx.x * blockDim.x + threadIdx.x;
    if (r < N_REL) {
        atomicAdd(&deg[rel[2*r+0]], 1.0f);
        atomicAdd(&deg[N_OBJ + rel[2*r+1]], 1.0f);
    }
}

// new_o = ofeat + 0.5*(acc0/degS + acc1/degO)
__global__ void update_o_kernel(const float* __restrict__ of, const float* __restrict__ a0,
                                const float* __restrict__ a1, const float* __restrict__ deg,
                                float* __restrict__ out, int ncols, int total) {
    int i = blockIdx.x * blockDim.x + threadIdx.x;
    if (i >= total) return;
    int r = i / ncols;
    out[i] = of[i] + 0.5f * (a0[i] / (deg[r] + 1e-7f) + a1[i] / (deg[N_OBJ + r] + 1e-7f));
}

// new_p = pfeat + 0.5*(fc0[subj] + fc1[obj]) / (1+1e-7)   (transposed-map degree == 1)
__global__ void update_p_kernel(const float* __restrict__ pf, const float* __restrict__ f0,
                                const float* __restrict__ f1, const int* __restrict__ rel,
                                float* __restrict__ out, int ncols, int total) {
    int i = blockIdx.x * blockDim.x + threadIdx.x;
    if (i >= total) return;
    int r = i / ncols;
    int c = i - r * ncols;
    int s = rel[2*r+0];
    int o = rel[2*r+1];
    out[i] = pf[i] + 0.5f * (f0[(size_t)s * ncols + c] + f1[(size_t)o * ncols + c]) / (1.0f + 1e-7f);
}

// ---------------- fast fp32 GEMM: C = op(A[MxK] @ W[KxN] + bias) --------------
// Requires M%128==0, N%64==0, K%16==0, 16B-aligned rows (true for all feature GEMMs).
// If sacc != nullptr: relu'd value is atomicAdd'ed into sacc[rel[r*2+sel]*N + c]
// (fused segment-sum epilogue, fc never materialized). Else stored to C.
__global__ __launch_bounds__(256)
void gemm128x64(const float* __restrict__ A, const float* __restrict__ W,
                const float* __restrict__ bias, int M, int K, int N, int doRelu,
                float* __restrict__ C,
                const int* __restrict__ rel, int sel, float* __restrict__ sacc) {
    __shared__ float As[16][128];
    __shared__ float Ws[16][64];

    const int tid = threadIdx.x;
    const int m0 = blockIdx.y * 128;
    const int n0 = blockIdx.x * 64;
    const int tm = tid >> 4;   // 0..15, 8 rows each
    const int tn = tid & 15;   // 0..15, 4 cols each

    float acc[8][4];
    #pragma unroll
    for (int i = 0; i < 8; i++)
        #pragma unroll
        for (int j = 0; j < 4; j++) acc[i][j] = 0.0f;

    for (int k0 = 0; k0 < K; k0 += 16) {
        // Load A tile 128x16 (transposed into As[k][row])
        #pragma unroll
        for (int t = 0; t < 2; t++) {
            int idx = tid * 2 + t;            // 0..511
            int row = idx >> 2;               // 0..127
            int kq  = idx & 3;                // 0..3 (float4 along K)
            float4 v = *(const float4*)(A + (size_t)(m0 + row) * K + k0 + kq * 4);
            As[kq*4+0][row] = v.x;
            As[kq*4+1][row] = v.y;
            As[kq*4+2][row] = v.z;
            As[kq*4+3][row] = v.w;
        }
        // Load W tile 16x64
        {
            int kr = tid >> 4;                // 0..15
            int nq = tid & 15;                // 0..15
            float4 v = *(const float4*)(W + (size_t)(k0 + kr) * N + n0 + nq * 4);
            *(float4*)&Ws[kr][nq*4] = v;
        }
        __syncthreads();

        #pragma unroll
        for (int k = 0; k < 16; k++) {
            float4 a0 = *(const float4*)&As[k][tm*8];
            float4 a1 = *(const float4*)&As[k][tm*8+4];
            float4 b  = *(const float4*)&Ws[k][tn*4];
            float av[8] = {a0.x, a0.y, a0.z, a0.w, a1.x, a1.y, a1.z, a1.w};
            float bv[4] = {b.x, b.y, b.z, b.w};
            #pragma unroll
            for (int i = 0; i < 8; i++)
                #pragma unroll
                for (int j = 0; j < 4; j++)
                    acc[i][j] = fmaf(av[i], bv[j], acc[i][j]);
        }
        __syncthreads();
    }

    // epilogue
    #pragma unroll
    for (int i = 0; i < 8; i++) {
        int r = m0 + tm * 8 + i;
        int tgt = 0;
        if (sacc) tgt = rel[r * 2 + sel];
        #pragma unroll
        for (int j = 0; j < 4; j++) {
            int c = n0 + tn * 4 + j;
            float v = acc[i][j] + bias[c];
            if (doRelu) v = fmaxf(v, 0.0f);
            if (sacc) atomicAdd(&sacc[(size_t)tgt * N + c], v);
            else      C[(size_t)r * N + c] = v;
        }
    }
}

// ---------------- small GEMM: one row per block (odd N / small K) -------------
// grid.x = M, blockDim.x = NT >= N (mult of 32), dyn smem = K*4 bytes.
__global__ void rowgemm_kernel(const float* __restrict__ A, const float* __restrict__ W,
                               const float* __restrict__ bias, int K, int N, int doRelu,
                               float* __restrict__ C,
                               const int* __restrict__ rel, int sel, float* __restrict__ sacc) {
    extern __shared__ float xs[];
    const int row = blockIdx.x;
    const float* arow = A + (size_t)row * K;
    for (int k = threadIdx.x; k < K; k += blockDim.x) xs[k] = arow[k];
    __syncthreads();
    const int col = threadIdx.x;
    if (col >= N) return;
    float acc = bias[col];
    #pragma unroll 4
    for (int k = 0; k < K; k++)
        acc = fmaf(xs[k], W[(size_t)k * N + col], acc);
    if (doRelu) acc = fmaxf(acc, 0.0f);
    if (sacc) {
        int t = rel[row * 2 + sel];
        atomicAdd(&sacc[(size_t)t * N + col], acc);
    } else {
        C[(size_t)row * N + col] = acc;
    }
}

// ---------------- host launch helpers -----------------------------------------
static inline void launch_zero(float* p, int n) {
    zero_kernel<<<(n + 255) / 256, 256>>>(p, n);
}
static inline void launch_gemm(const float* A, const float* W, const float* b,
                               int M, int K, int N, int relu,
                               float* C, const int* rel, int sel, float* sacc) {
    dim3 grid(N / 64, M / 128);
    gemm128x64<<<grid, 256>>>(A, W, b, M, K, N, relu, C, rel, sel, sacc);
}
static inline void launch_rowgemm(const float* A, const float* W, const float* b,
                                  int M, int K, int N, int relu,
                                  float* C, const int* rel, int sel, float* sacc) {
    int nt = ((N + 31) / 32) * 32;
    rowgemm_kernel<<<M, nt, K * (int)sizeof(float)>>>(A, W, b, K, N, relu, C, rel, sel, sacc);
}

template <typename T>
static inline T* sym(const void* s) {
    void* p = nullptr;
    cudaGetSymbolAddress(&p, s);
    return (T*)p;
}

extern "C" void kernel_launch(void* const* d_in, const int* in_sizes, int n_in,
                              void* d_out, int out_size) {
    const float* x_obj_raw  = (const float*)d_in[0];
    const float* x_pred_raw = (const float*)d_in[1];
    const int*   rel        = (const int*)  d_in[2];
    const float* oW1 = (const float*)d_in[3],  *ob1 = (const float*)d_in[4];
    const float* oW2 = (const float*)d_in[5],  *ob2 = (const float*)d_in[6];
    const float* rW1 = (const float*)d_in[7],  *rb1 = (const float*)d_in[8];
    const float* rW2 = (const float*)d_in[9],  *rb2 = (const float*)d_in[10];
    const float* Wcf = (const float*)d_in[11], *bcf = (const float*)d_in[12];
    const float* Wso = (const float*)d_in[13], *bso = (const float*)d_in[14];
    const float* Wsr = (const float*)d_in[15], *bsr = (const float*)d_in[16];
    const float* Woc = (const float*)d_in[17], *boc = (const float*)d_in[18];
    const float* Wpc = (const float*)d_in[19], *bpc = (const float*)d_in[20];
    float* out = (float*)d_out;

    float* hpred  = sym<float>(g_hpred);
    float* pfA    = sym<float>(g_pfeatA);
    float* pfB    = sym<float>(g_pfeatB);
    float* hobj   = sym<float>(g_hobj);
    float* ofA    = sym<float>(g_ofeatA);
    float* ofB    = sym<float>(g_ofeatB);
    float* fco0   = sym<float>(g_fco0);
    float* fco1   = sym<float>(g_fco1);
    float* acc0   = sym<float>(g_acc0);
    float* acc1   = sym<float>(g_acc1);
    float* osA    = sym<float>(g_osA);
    float* osB    = sym<float>(g_osB);
    float* psA    = sym<float>(g_psA);
    float* psB    = sym<float>(g_psB);
    float* sacc0  = sym<float>(g_sacc0);
    float* sacc1  = sym<float>(g_sacc1);
    float* fcs0   = sym<float>(g_fcs0);
    float* fcs1   = sym<float>(g_fcs1);
    float* deg    = sym<float>(g_deg);

    // ---- degrees ----
    launch_zero(deg, 2 * N_OBJ);
    deg_kernel<<<(N_REL + 255) / 256, 256>>>(rel, deg);

    // ---- embedding MLPs ----
    // obj: [2048,2048]@[2048,512] relu -> hobj; hobj@[512,512] -> ofeat
    launch_gemm(x_obj_raw, oW1, ob1, N_OBJ, FEAT, DIM, 1, hobj, nullptr, 0, nullptr);
    launch_gemm(hobj,      oW2, ob2, N_OBJ, DIM,  DIM, 0, ofA,  nullptr, 0, nullptr);
    // pred: [32768,2048]@[2048,512] relu -> hpred; hpred@[512,512] -> pfeat
    launch_gemm(x_pred_raw, rW1, rb1, N_REL, FEAT, DIM, 1, hpred, nullptr, 0, nullptr);
    launch_gemm(hpred,      rW2, rb2, N_REL, DIM,  DIM, 0, pfA,   nullptr, 0, nullptr);
    // x_pred output (output #0)
    copy_kernel<<<(N_REL * DIM + 255) / 256, 256>>>(out, pfA, N_REL * DIM);

    // ---- feature-level aGCN (2 steps) ----
    float* of = ofA; float* ofn = ofB;
    float* pf = pfA; float* pfn = pfB;
    for (int st = 0; st < 2; st++) {
        launch_zero(acc0, N_OBJ * DIM);
        launch_zero(acc1, N_OBJ * DIM);
        // relu(pfeat @ Wc0 + b0) scattered by subj / obj (fused epilogue)
        launch_gemm(pf, Wcf + 0 * DIM * DIM, bcf + 0 * DIM, N_REL, DIM, DIM, 1,
                    nullptr, rel, 0, acc0);
        launch_gemm(pf, Wcf + 1 * DIM * DIM, bcf + 1 * DIM, N_REL, DIM, DIM, 1,
                    nullptr, rel, 1, acc1);
        update_o_kernel<<<(N_OBJ * DIM + 255) / 256, 256>>>(of, acc0, acc1, deg, ofn,
                                                            DIM, N_OBJ * DIM);
        // relu(ofeat @ Wc2/3 + b) then gather by subj/obj
        launch_gemm(of, Wcf + 2 * DIM * DIM, bcf + 2 * DIM, N_OBJ, DIM, DIM, 1,
                    fco0, nullptr, 0, nullptr);
        launch_gemm(of, Wcf + 3 * DIM * DIM, bcf + 3 * DIM, N_OBJ, DIM, DIM, 1,
                    fco1, nullptr, 0, nullptr);
        update_p_kernel<<<(N_REL * DIM + 255) / 256, 256>>>(pf, fco0, fco1, rel, pfn,
                                                            DIM, N_REL * DIM);
        float* t;
        t = of; of = ofn; ofn = t;
        t = pf; pf = pfn; pfn = t;
    }

    // ---- classifiers ----
    launch_rowgemm(of, Woc, boc, N_OBJ, DIM, NC_OBJ,  0, osA, nullptr, 0, nullptr);
    launch_rowgemm(pf, Wpc, bpc, N_REL, DIM, NC_PRED, 0, psA, nullptr, 0, nullptr);

    // ---- score-level aGCN (2 steps) ----
    float* os = osA; float* osn = osB;
    float* ps = psA; float* psn = psB;
    for (int st = 0; st < 2; st++) {
        launch_zero(sacc0, N_OBJ * NC_OBJ);
        launch_zero(sacc1, N_OBJ * NC_OBJ);
        // relu(ps @ Wso[s] + b) [32768,151], scatter by subj/obj
        launch_rowgemm(ps, Wso + 0 * NC_PRED * NC_OBJ, bso + 0 * NC_OBJ,
                       N_REL, NC_PRED, NC_OBJ, 1, nullptr, rel, 0, sacc0);
        launch_rowgemm(ps, Wso + 1 * NC_PRED * NC_OBJ, bso + 1 * NC_OBJ,
                       N_REL, NC_PRED, NC_OBJ, 1, nullptr, rel, 1, sacc1);
        update_o_kernel<<<(N_OBJ * NC_OBJ + 255) / 256, 256>>>(os, sacc0, sacc1, deg, osn,
                                                               NC_OBJ, N_OBJ * NC_OBJ);
        // relu(os @ Wsr[s] + b) [2048,51], gather by subj/obj
        launch_rowgemm(os, Wsr + 0 * NC_OBJ * NC_PRED, bsr + 0 * NC_PRED,
                       N_OBJ, NC_OBJ, NC_PRED, 1, fcs0, nullptr, 0, nullptr);
        launch_rowgemm(os, Wsr + 1 * NC_OBJ * NC_PRED, bsr + 1 * NC_PRED,
                       N_OBJ, NC_OBJ, NC_PRED, 1, fcs1, nullptr, 0, nullptr);
        update_p_kernel<<<(N_REL * NC_PRED + 255) / 256, 256>>>(ps, fcs0, fcs1, rel, psn,
                                                                NC_PRED, N_REL * NC_PRED);
        float* t;
        t = os; os = osn; osn = t;
        t = ps; ps = psn; psn = t;
    }

    // ---- outputs #1 and #2 ----
    copy_kernel<<<(N_OBJ * NC_OBJ + 255) / 256, 256>>>(out + (size_t)N_REL * DIM,
                                                       os, N_OBJ * NC_OBJ);
    copy_kernel<<<(N_REL * NC_PRED + 255) / 256, 256>>>(out + (size_t)N_REL * DIM + N_OBJ * NC_OBJ,
                                                        ps, N_REL * NC_PRED);
}

// round 3
// speedup vs baseline: 2.0310x; 2.0310x over previous
#include <cuda_runtime.h>
#include <cstdint>
#include <math.h>

#define N_OBJ   2048
#define N_REL   32768
#define FEAT    2048
#define DIM     512
#define NC_OBJ  151
#define NC_PRED 51

// ---------------- scratch (static device globals; no allocation) -------------
__device__ __align__(128) float g_hpred [N_REL*DIM];
__device__ __align__(128) float g_pfeatA[N_REL*DIM];
__device__ __align__(128) float g_pfeatB[N_REL*DIM];
__device__ __align__(128) float g_hobj  [N_OBJ*DIM];
__device__ __align__(128) float g_ofeatA[N_OBJ*DIM];
__device__ __align__(128) float g_ofeatB[N_OBJ*DIM];
__device__ __align__(128) float g_fco0  [N_OBJ*DIM];
__device__ __align__(128) float g_fco1  [N_OBJ*DIM];
__device__ __align__(128) float g_acc0  [N_OBJ*DIM];
__device__ __align__(128) float g_acc1  [N_OBJ*DIM];
__device__ __align__(128) float g_osA   [N_OBJ*NC_OBJ];
__device__ __align__(128) float g_osB   [N_OBJ*NC_OBJ];
__device__ __align__(128) float g_psA   [N_REL*NC_PRED];
__device__ __align__(128) float g_psB   [N_REL*NC_PRED];
__device__ __align__(128) float g_sacc0 [N_OBJ*NC_OBJ];
__device__ __align__(128) float g_sacc1 [N_OBJ*NC_OBJ];
__device__ __align__(128) float g_fcs0  [N_OBJ*NC_PRED];
__device__ __align__(128) float g_fcs1  [N_OBJ*NC_PRED];
__device__ __align__(128) float g_deg   [2*N_OBJ];

// ---------------- helpers ------------------------------------------------------
__device__ __forceinline__ uint32_t smem_u32(const void* p) {
    uint32_t a;
    asm("{ .reg .u64 t; cvta.to.shared.u64 t, %1; cvt.u32.u64 %0, t; }" : "=r"(a) : "l"(p));
    return a;
}
// pack {hi16=bf16(y), lo16=bf16(x)} -> memory order x then y (little endian)
__device__ __forceinline__ uint32_t pack_bf16x2(float x, float y) {
    uint32_t d;
    asm("cvt.rn.bf16x2.f32 %0, %1, %2;" : "=r"(d) : "f"(y), "f"(x));
    return d;
}
__device__ __forceinline__ void split_pair(float x, float y, uint32_t& hi, uint32_t& lo) {
    hi = pack_bf16x2(x, y);
    float hx = __uint_as_float((hi & 0xffffu) << 16);
    float hy = __uint_as_float(hi & 0xffff0000u);
    lo = pack_bf16x2(x - hx, y - hy);
}
__device__ __forceinline__ void ldsm_x4(uint32_t* r, uint32_t addr) {
    asm volatile("ldmatrix.sync.aligned.m8n8.x4.shared.b16 {%0,%1,%2,%3}, [%4];"
                 : "=r"(r[0]), "=r"(r[1]), "=r"(r[2]), "=r"(r[3]) : "r"(addr));
}
__device__ __forceinline__ void ldsm_x4_t(uint32_t* r, uint32_t addr) {
    asm volatile("ldmatrix.sync.aligned.m8n8.x4.trans.shared.b16 {%0,%1,%2,%3}, [%4];"
                 : "=r"(r[0]), "=r"(r[1]), "=r"(r[2]), "=r"(r[3]) : "r"(addr));
}
__device__ __forceinline__ void mma16816(float* c, const uint32_t* a, uint32_t b0, uint32_t b1) {
    asm volatile("mma.sync.aligned.m16n8k16.row.col.f32.bf16.bf16.f32 "
                 "{%0,%1,%2,%3}, {%4,%5,%6,%7}, {%8,%9}, {%0,%1,%2,%3};"
                 : "+f"(c[0]), "+f"(c[1]), "+f"(c[2]), "+f"(c[3])
                 : "r"(a[0]), "r"(a[1]), "r"(a[2]), "r"(a[3]), "r"(b0), "r"(b1));
}

// ---------------- bf16-split tensor GEMM --------------------------------------
// C[M,N] = op(A[M,K] @ W[K,N] + bias),  M%128==0, N%128==0, K%32==0.
// fp32 inputs split into bf16 hi+lo; 3 mma passes -> ~1e-5 rel accuracy.
// If sacc: relu'd value atomicAdd'ed to sacc[rel[r*2+sel]*N + c]; else stored to C.
#define APITCH 80    // bytes per A row (32 bf16 = 64B + 16B pad) -> conflict-free ldmatrix
#define BPITCH 272   // bytes per B row (128 bf16 = 256B + 16B pad)
#define ST_AHI 0
#define ST_ALO 10240
#define ST_BHI 20480
#define ST_BLO 29184
#define ST_SZ  37888
#define SMEM_GEMM (2*ST_SZ)

__global__ __launch_bounds__(256)
void gemm_bf16s(const float* __restrict__ A, const float* __restrict__ W,
                const float* __restrict__ bias, int M, int K, int N, int doRelu,
                float* __restrict__ C,
                const int* __restrict__ rel, int sel, float* __restrict__ sacc) {
    extern __shared__ char smem[];
    const uint32_t sb = smem_u32(smem);
    const int tid = threadIdx.x;
    const int lane = tid & 31;
    const int w = tid >> 5;
    const int warp_m = (w & 1) * 64;
    const int warp_n = (w >> 1) * 32;
    const int m0 = blockIdx.y * 128;
    const int n0 = blockIdx.x * 128;

    float acc[16][4];
    #pragma unroll
    for (int i = 0; i < 16; i++)
        #pragma unroll
        for (int j = 0; j < 4; j++) acc[i][j] = 0.0f;

    float4 ra[4], rb[4];

    // global load of tile kt into regs
    auto ldg_tile = [&](int kt) {
        #pragma unroll
        for (int i = 0; i < 4; i++) {
            int f = (i * 256 + tid) * 4;
            ra[i] = *(const float4*)(A + (size_t)(m0 + (f >> 5)) * K + kt * 32 + (f & 31));
            rb[i] = *(const float4*)(W + (size_t)(kt * 32 + (f >> 7)) * N + n0 + (f & 127));
        }
    };
    // split + store regs into stage s
    auto sts_tile = [&](int s) {
        const uint32_t st = sb + s * ST_SZ;
        #pragma unroll
        for (int i = 0; i < 4; i++) {
            int f = (i * 256 + tid) * 4;
            // A: row f>>5, col f&31
            {
                uint32_t h0, l0, h1, l1;
                split_pair(ra[i].x, ra[i].y, h0, l0);
                split_pair(ra[i].z, ra[i].w, h1, l1);
                uint32_t off = (uint32_t)((f >> 5) * APITCH + (f & 31) * 2);
                asm volatile("st.shared.v2.b32 [%0], {%1,%2};" :: "r"(st + ST_AHI + off), "r"(h0), "r"(h1) : "memory");
                asm volatile("st.shared.v2.b32 [%0], {%1,%2};" :: "r"(st + ST_ALO + off), "r"(l0), "r"(l1) : "memory");
            }
            // B: row f>>7, col f&127
            {
                uint32_t h0, l0, h1, l1;
                split_pair(rb[i].x, rb[i].y, h0, l0);
                split_pair(rb[i].z, rb[i].w, h1, l1);
                uint32_t off = (uint32_t)((f >> 7) * BPITCH + (f & 127) * 2);
                asm volatile("st.shared.v2.b32 [%0], {%1,%2};" :: "r"(st + ST_BHI + off), "r"(h0), "r"(h1) : "memory");
                asm volatile("st.shared.v2.b32 [%0], {%1,%2};" :: "r"(st + ST_BLO + off), "r"(l0), "r"(l1) : "memory");
            }
        }
    };

    ldg_tile(0);
    sts_tile(0);
    __syncthreads();

    const int KT = K >> 5;
    for (int kt = 0; kt < KT; kt++) {
        const int s = kt & 1;
        if (kt + 1 < KT) ldg_tile(kt + 1);

        const uint32_t st = sb + s * ST_SZ;
        #pragma unroll
        for (int ks = 0; ks < 2; ks++) {
            // A fragments (hi & lo) for 4 m-frags
            uint32_t ah[4][4], al[4][4];
            const uint32_t a_off = (uint32_t)((warp_m + (lane & 15)) * APITCH
                                              + ks * 32 + (lane >> 4) * 16);
            #pragma unroll
            for (int mi = 0; mi < 4; mi++) {
                ldsm_x4(ah[mi], st + ST_AHI + a_off + mi * 16 * APITCH);
                ldsm_x4(al[mi], st + ST_ALO + a_off + mi * 16 * APITCH);
            }
            // B fragments: 2 pairs of n-frags
            const uint32_t b_off = (uint32_t)((ks * 16 + (lane & 15)) * BPITCH
                                              + (warp_n + (lane >> 4) * 8) * 2);
            #pragma unroll
            for (int np = 0; np < 2; np++) {
                uint32_t bh[4], bl[4];
                ldsm_x4_t(bh, st + ST_BHI + b_off + np * 32);
                ldsm_x4_t(bl, st + ST_BLO + b_off + np * 32);
                #pragma unroll
                for (int mi = 0; mi < 4; mi++) {
                    #pragma unroll
                    for (int j = 0; j < 2; j++) {
                        float* c = acc[mi * 4 + np * 2 + j];
                        mma16816(c, ah[mi], bh[2*j], bh[2*j+1]);
                        mma16816(c, ah[mi], bl[2*j], bl[2*j+1]);
                        mma16816(c, al[mi], bh[2*j], bh[2*j+1]);
                    }
                }
            }
        }

        if (kt + 1 < KT) sts_tile(s ^ 1);
        __syncthreads();
    }

    // ---- epilogue ----
    const int g = lane >> 2, tig = lane & 3;
    #pragma unroll
    for (int mi = 0; mi < 4; mi++) {
        const int r0 = m0 + warp_m + mi * 16 + g;
        const int r1 = r0 + 8;
        int t0 = 0, t1 = 0;
        if (sacc) { t0 = rel[r0 * 2 + sel]; t1 = rel[r1 * 2 + sel]; }
        #pragma unroll
        for (int ni = 0; ni < 4; ni++) {
            const int c = n0 + warp_n + ni * 8 + tig * 2;
            float b0 = bias[c], b1 = bias[c + 1];
            float* a = acc[mi * 4 + ni];
            float v0 = a[0] + b0, v1 = a[1] + b1, v2 = a[2] + b0, v3 = a[3] + b1;
            if (doRelu) {
                v0 = fmaxf(v0, 0.0f); v1 = fmaxf(v1, 0.0f);
                v2 = fmaxf(v2, 0.0f); v3 = fmaxf(v3, 0.0f);
            }
            if (sacc) {
                atomicAdd(&sacc[(size_t)t0 * N + c],     v0);
                atomicAdd(&sacc[(size_t)t0 * N + c + 1], v1);
                atomicAdd(&sacc[(size_t)t1 * N + c],     v2);
                atomicAdd(&sacc[(size_t)t1 * N + c + 1], v3);
            } else {
                *(float2*)(C + (size_t)r0 * N + c) = make_float2(v0, v1);
                *(float2*)(C + (size_t)r1 * N + c) = make_float2(v2, v3);
            }
        }
    }
}

// ---------------- small utility kernels --------------------------------------
__global__ void zero_kernel(float* p, int n) {
    int i = blockIdx.x * blockDim.x + threadIdx.x;
    if (i < n) p[i] = 0.0f;
}
__global__ void copy_kernel(float* __restrict__ dst, const float* __restrict__ src, int n) {
    int i = blockIdx.x * blockDim.x + threadIdx.x;
    if (i < n) dst[i] = src[i];
}
__global__ void deg_kernel(const int* __restrict__ rel, float* __restrict__ deg) {
    int r = blockIdx.x * blockDim.x + threadIdx.x;
    if (r < N_REL) {
        atomicAdd(&deg[rel[2*r+0]], 1.0f);
        atomicAdd(&deg[N_OBJ + rel[2*r+1]], 1.0f);
    }
}
__global__ void update_o_kernel(const float* __restrict__ of, const float* __restrict__ a0,
                                const float* __restrict__ a1, const float* __restrict__ deg,
                                float* __restrict__ out, int ncols, int total) {
    int i = blockIdx.x * blockDim.x + threadIdx.x;
    if (i >= total) return;
    int r = i / ncols;
    out[i] = of[i] + 0.5f * (a0[i] / (deg[r] + 1e-7f) + a1[i] / (deg[N_OBJ + r] + 1e-7f));
}
__global__ void update_p_kernel(const float* __restrict__ pf, const float* __restrict__ f0,
                                const float* __restrict__ f1, const int* __restrict__ rel,
                                float* __restrict__ out, int ncols, int total) {
    int i = blockIdx.x * blockDim.x + threadIdx.x;
    if (i >= total) return;
    int r = i / ncols;
    int c = i - r * ncols;
    int s = rel[2*r+0];
    int o = rel[2*r+1];
    out[i] = pf[i] + 0.5f * (f0[(size_t)s * ncols + c] + f1[(size_t)o * ncols + c]) / (1.0f + 1e-7f);
}

// ---------------- small GEMM: one row per block (odd N / small K) -------------
__global__ void rowgemm_kernel(const float* __restrict__ A, const float* __restrict__ W,
                               const float* __restrict__ bias, int K, int N, int doRelu,
                               float* __restrict__ C,
                               const int* __restrict__ rel, int sel, float* __restrict__ sacc) {
    extern __shared__ float xs[];
    const int row = blockIdx.x;
    const float* arow = A + (size_t)row * K;
    for (int k = threadIdx.x; k < K; k += blockDim.x) xs[k] = arow[k];
    __syncthreads();
    const int col = threadIdx.x;
    if (col >= N) return;
    float acc = bias[col];
    #pragma unroll 4
    for (int k = 0; k < K; k++)
        acc = fmaf(xs[k], W[(size_t)k * N + col], acc);
    if (doRelu) acc = fmaxf(acc, 0.0f);
    if (sacc) {
        int t = rel[row * 2 + sel];
        atomicAdd(&sacc[(size_t)t * N + col], acc);
    } else {
        C[(size_t)row * N + col] = acc;
    }
}

// ---------------- host launch helpers -----------------------------------------
static inline void launch_zero(float* p, int n) {
    zero_kernel<<<(n + 255) / 256, 256>>>(p, n);
}
static inline void launch_gemm(const float* A, const float* W, const float* b,
                               int M, int K, int N, int relu,
                               float* C, const int* rel, int sel, float* sacc) {
    dim3 grid(N / 128, M / 128);
    gemm_bf16s<<<grid, 256, SMEM_GEMM>>>(A, W, b, M, K, N, relu, C, rel, sel, sacc);
}
static inline void launch_rowgemm(const float* A, const float* W, const float* b,
                                  int M, int K, int N, int relu,
                                  float* C, const int* rel, int sel, float* sacc) {
    int nt = ((N + 31) / 32) * 32;
    rowgemm_kernel<<<M, nt, K * (int)sizeof(float)>>>(A, W, b, K, N, relu, C, rel, sel, sacc);
}
template <typename T>
static inline T* sym(const void* s) {
    void* p = nullptr;
    cudaGetSymbolAddress(&p, s);
    return (T*)p;
}

extern "C" void kernel_launch(void* const* d_in, const int* in_sizes, int n_in,
                              void* d_out, int out_size) {
    const float* x_obj_raw  = (const float*)d_in[0];
    const float* x_pred_raw = (const float*)d_in[1];
    const int*   rel        = (const int*)  d_in[2];
    const float* oW1 = (const float*)d_in[3],  *ob1 = (const float*)d_in[4];
    const float* oW2 = (const float*)d_in[5],  *ob2 = (const float*)d_in[6];
    const float* rW1 = (const float*)d_in[7],  *rb1 = (const float*)d_in[8];
    const float* rW2 = (const float*)d_in[9],  *rb2 = (const float*)d_in[10];
    const float* Wcf = (const float*)d_in[11], *bcf = (const float*)d_in[12];
    const float* Wso = (const float*)d_in[13], *bso = (const float*)d_in[14];
    const float* Wsr = (const float*)d_in[15], *bsr = (const float*)d_in[16];
    const float* Woc = (const float*)d_in[17], *boc = (const float*)d_in[18];
    const float* Wpc = (const float*)d_in[19], *bpc = (const float*)d_in[20];
    float* out = (float*)d_out;

    // host-side, idempotent, stream-independent: safe under graph capture
    cudaFuncSetAttribute(gemm_bf16s, cudaFuncAttributeMaxDynamicSharedMemorySize, SMEM_GEMM);

    float* hpred  = sym<float>(g_hpred);
    float* pfA    = sym<float>(g_pfeatA);
    float* pfB    = sym<float>(g_pfeatB);
    float* hobj   = sym<float>(g_hobj);
    float* ofA    = sym<float>(g_ofeatA);
    float* ofB    = sym<float>(g_ofeatB);
    float* fco0   = sym<float>(g_fco0);
    float* fco1   = sym<float>(g_fco1);
    float* acc0   = sym<float>(g_acc0);
    float* acc1   = sym<float>(g_acc1);
    float* osA    = sym<float>(g_osA);
    float* osB    = sym<float>(g_osB);
    float* psA    = sym<float>(g_psA);
    float* psB    = sym<float>(g_psB);
    float* sacc0  = sym<float>(g_sacc0);
    float* sacc1  = sym<float>(g_sacc1);
    float* fcs0   = sym<float>(g_fcs0);
    float* fcs1   = sym<float>(g_fcs1);
    float* deg    = sym<float>(g_deg);

    // ---- degrees ----
    launch_zero(deg, 2 * N_OBJ);
    deg_kernel<<<(N_REL + 255) / 256, 256>>>(rel, deg);

    // ---- embedding MLPs ----
    launch_gemm(x_obj_raw, oW1, ob1, N_OBJ, FEAT, DIM, 1, hobj, nullptr, 0, nullptr);
    launch_gemm(hobj,      oW2, ob2, N_OBJ, DIM,  DIM, 0, ofA,  nullptr, 0, nullptr);
    launch_gemm(x_pred_raw, rW1, rb1, N_REL, FEAT, DIM, 1, hpred, nullptr, 0, nullptr);
    // pred MLP layer 2 writes x_pred directly into out (output #0)
    launch_gemm(hpred,      rW2, rb2, N_REL, DIM,  DIM, 0, out,   nullptr, 0, nullptr);

    // ---- feature-level aGCN (2 steps) ----
    float* of = ofA;  float* ofn = ofB;
    float* pf = out;  float* pfn = pfB;
    for (int st = 0; st < 2; st++) {
        launch_zero(acc0, N_OBJ * DIM);
        launch_zero(acc1, N_OBJ * DIM);
        launch_gemm(pf, Wcf + 0 * DIM * DIM, bcf + 0 * DIM, N_REL, DIM, DIM, 1,
                    nullptr, rel, 0, acc0);
        launch_gemm(pf, Wcf + 1 * DIM * DIM, bcf + 1 * DIM, N_REL, DIM, DIM, 1,
                    nullptr, rel, 1, acc1);
        update_o_kernel<<<(N_OBJ * DIM + 255) / 256, 256>>>(of, acc0, acc1, deg, ofn,
                                                            DIM, N_OBJ * DIM);
        launch_gemm(of, Wcf + 2 * DIM * DIM, bcf + 2 * DIM, N_OBJ, DIM, DIM, 1,
                    fco0, nullptr, 0, nullptr);
        launch_gemm(of, Wcf + 3 * DIM * DIM, bcf + 3 * DIM, N_OBJ, DIM, DIM, 1,
                    fco1, nullptr, 0, nullptr);
        update_p_kernel<<<(N_REL * DIM + 255) / 256, 256>>>(pf, fco0, fco1, rel, pfn,
                                                            DIM, N_REL * DIM);
        float* t;
        t = of; of = ofn; ofn = t;
        pf = pfn; pfn = (st == 0) ? pfA : pfB;
    }

    // ---- classifiers ----
    launch_rowgemm(of, Woc, boc, N_OBJ, DIM, NC_OBJ,  0, osA, nullptr, 0, nullptr);
    launch_rowgemm(pf, Wpc, bpc, N_REL, DIM, NC_PRED, 0, psA, nullptr, 0, nullptr);

    // ---- score-level aGCN (2 steps) ----
    float* os = osA; float* osn = osB;
    float* ps = psA; float* psn = psB;
    for (int st = 0; st < 2; st++) {
        launch_zero(sacc0, N_OBJ * NC_OBJ);
        launch_zero(sacc1, N_OBJ * NC_OBJ);
        launch_rowgemm(ps, Wso + 0 * NC_PRED * NC_OBJ, bso + 0 * NC_OBJ,
                       N_REL, NC_PRED, NC_OBJ, 1, nullptr, rel, 0, sacc0);
        launch_rowgemm(ps, Wso + 1 * NC_PRED * NC_OBJ, bso + 1 * NC_OBJ,
                       N_REL, NC_PRED, NC_OBJ, 1, nullptr, rel, 1, sacc1);
        update_o_kernel<<<(N_OBJ * NC_OBJ + 255) / 256, 256>>>(os, sacc0, sacc1, deg, osn,
                                                               NC_OBJ, N_OBJ * NC_OBJ);
        launch_rowgemm(os, Wsr + 0 * NC_OBJ * NC_PRED, bsr + 0 * NC_PRED,
                       N_OBJ, NC_OBJ, NC_PRED, 1, fcs0, nullptr, 0, nullptr);
        launch_rowgemm(os, Wsr + 1 * NC_OBJ * NC_PRED, bsr + 1 * NC_PRED,
                       N_OBJ, NC_OBJ, NC_PRED, 1, fcs1, nullptr, 0, nullptr);
        update_p_kernel<<<(N_REL * NC_PRED + 255) / 256, 256>>>(ps, fcs0, fcs1, rel, psn,
                                                                NC_PRED, N_REL * NC_PRED);
        float* t;
        t = os; os = osn; osn = t;
        t = ps; ps = psn; psn = t;
    }

    // ---- outputs #1 and #2 ----
    copy_kernel<<<(N_OBJ * NC_OBJ + 255) / 256, 256>>>(out + (size_t)N_REL * DIM,
                                                       os, N_OBJ * NC_OBJ);
    copy_kernel<<<(N_REL * NC_PRED + 255) / 256, 256>>>(out + (size_t)N_REL * DIM + N_OBJ * NC_OBJ,
                                                        ps, N_REL * NC_PRED);
}